// round 16
// baseline (speedup 1.0000x reference)
#include <cuda_runtime.h>

// EfficientAttention fused kernel (sm_100a).
// R16: T=5 conv with PERFECT warp alignment. 512 thr: warp = 8-channel
// chunk (16 warps), lane = j-quintet (32x5 = all 160 j). Every K LDS.128 is
// a true single-wavefront broadcast (one K row per warp); q loads are
// stride-5 (coprime 32) -> bank-conflict-free. 22 smem wavefronts per
// 125 fma2 (was 35 per 50). Full-row CTAs (512 blocks), R3 load/softmax/
// gather bodies (gather: 8 k-groups x 20 j).

#define NTHR  512
#define QROW  165          // [2 zero | 160 data | 3 zero], odd stride
#define KROW  52
#define W_OFF1   5242880   // 4*128*160*64
#define W_OFF2   6062080   // W_OFF1 + 512*160*10

__device__ __forceinline__ unsigned long long pack2(float lo, float hi) {
    unsigned long long r;
    asm("mov.b64 %0, {%1, %2};" : "=l"(r) : "f"(lo), "f"(hi));
    return r;
}
__device__ __forceinline__ void unpack2(unsigned long long v, float& lo, float& hi) {
    asm("mov.b64 {%0, %1}, %2;" : "=f"(lo), "=f"(hi) : "l"(v));
}
__device__ __forceinline__ void fma2(unsigned long long& d, unsigned long long a,
                                     unsigned long long b) {
    asm("fma.rn.f32x2 %0, %1, %2, %3;" : "=l"(d) : "l"(a), "l"(b), "l"(d));
}

__global__ void __launch_bounds__(NTHR, 1)
ea_kernel(const float* __restrict__ gL, const float* __restrict__ gR,
          const float* __restrict__ gK, const float* __restrict__ gBias,
          const float* __restrict__ gGamma, const float* __restrict__ gBeta,
          const float* __restrict__ gMean, const float* __restrict__ gVar,
          float* __restrict__ out)
{
    extern __shared__ float sm[];
    float* Qt = sm;                        // 128*165 (L ch 0..63, R ch 64..127)
    float* Kc = Qt + 128 * QROW;           // 128*52:  Kc[c][w*10+m]
    float* W4 = Kc + 128 * KROW;           // 8*160*11: logit partials
    float* WS = W4 + 8 * 160 * 11;         // 160*12:  softmaxed weights

    const int t   = threadIdx.x;
    const int row = blockIdx.x;            // n*H + i
    const float* Lrow = gL + (size_t)row * 10240;
    const float* Rrow = gR + (size_t)row * 10240;

    // ---- zero SAME-conv padding cols (128 ch x 5 = 640) ----
    for (int z = t; z < 640; z += NTHR) {
        int c = z / 5, pc = z % 5;
        int col = (pc < 2) ? pc : (pc + 160);
        Qt[c * QROW + col] = 0.f;
    }

    // ---- load L,R rows (coalesced float4) -> transposed smem ----
    #pragma unroll
    for (int kk = 0; kk < 5; kk++) {
        int i4 = t + kk * NTHR;                    // 0..2559 = j*16 + cquad
        int j = i4 >> 4, c = (i4 & 15) << 2;
        float4 v = reinterpret_cast<const float4*>(Lrow)[i4];
        Qt[(c + 0) * QROW + 2 + j] = v.x;
        Qt[(c + 1) * QROW + 2 + j] = v.y;
        Qt[(c + 2) * QROW + 2 + j] = v.z;
        Qt[(c + 3) * QROW + 2 + j] = v.w;
        float4 u = reinterpret_cast<const float4*>(Rrow)[i4];
        Qt[(c + 64) * QROW + 2 + j] = u.x;
        Qt[(c + 65) * QROW + 2 + j] = u.y;
        Qt[(c + 66) * QROW + 2 + j] = u.z;
        Qt[(c + 67) * QROW + 2 + j] = u.w;
    }

    // ---- load conv kernel, HWIO (w,c,m) -> Kc[c][w*10+m] ----
    for (int g = t; g < 6400; g += NTHR) {
        int m = g % 10;
        int c = (g / 10) & 127;
        int w = g / 1280;
        Kc[c * KROW + w * 10 + m] = gK[g];
    }
    __syncthreads();

    // ---- conv: warp = 8-channel chunk, lane = j-quintet (j0 = 5*lane) ----
    const int cw   = t >> 5;               // warp id 0..15 = channel chunk
    const int lane = t & 31;
    {
        unsigned long long acc[5][5];      // [j][m-pair]
        #pragma unroll
        for (int j = 0; j < 5; j++)
            #pragma unroll
            for (int p = 0; p < 5; p++) acc[j][p] = 0ull;

        // window for outputs j0..j0+4 = padded cols 5*lane .. 5*lane+8
        const float* qbase = Qt + (cw * 8) * QROW + 5 * lane;
        const float* kbase = Kc + (cw * 8) * KROW;

        #pragma unroll 2
        for (int ci = 0; ci < 8; ci++) {
            const float* q = qbase + ci * QROW;
            unsigned long long pk[9];
            #pragma unroll
            for (int w = 0; w < 9; w++) pk[w] = pack2(q[w], q[w]);

            const float* krow = kbase + ci * KROW;
            const ulonglong2* kp = reinterpret_cast<const ulonglong2*>(krow);
            #pragma unroll
            for (int i = 0; i < 12; i++) {
                ulonglong2 kv = kp[i];     // single-wavefront broadcast
                const int pi0 = 2 * i, pi1 = 2 * i + 1;
                const int p0 = pi0 % 5, w0 = pi0 / 5;
                const int p1 = pi1 % 5, w1 = pi1 / 5;
                #pragma unroll
                for (int j = 0; j < 5; j++) {
                    fma2(acc[j][p0], pk[w0 + j], kv.x);
                    fma2(acc[j][p1], pk[w1 + j], kv.y);
                }
            }
            unsigned long long kl =
                reinterpret_cast<const unsigned long long*>(krow)[24]; // w=4,p=4
            #pragma unroll
            for (int j = 0; j < 5; j++)
                fma2(acc[j][4], pk[4 + j], kl);
        }

        // two-pass fold into 8 W4 groups: warps 0-7 write, 8-15 accumulate
        const int grp = cw & 7;
        if (cw < 8) {
            #pragma unroll
            for (int j = 0; j < 5; j++) {
                float* wd = W4 + (grp * 160 + 5 * lane + j) * 11;
                #pragma unroll
                for (int p = 0; p < 5; p++) {
                    float lo, hi;
                    unpack2(acc[j][p], lo, hi);
                    wd[2 * p] = lo; wd[2 * p + 1] = hi;
                }
            }
        }
        __syncthreads();
        if (cw >= 8) {
            #pragma unroll
            for (int j = 0; j < 5; j++) {
                float* wd = W4 + (grp * 160 + 5 * lane + j) * 11;
                #pragma unroll
                for (int p = 0; p < 5; p++) {
                    float lo, hi;
                    unpack2(acc[j][p], lo, hi);
                    wd[2 * p]     += lo;
                    wd[2 * p + 1] += hi;
                }
            }
        }
    }
    __syncthreads();

    // ---- logit reduction + softmax + weight outputs (threads 0..159) ----
    if (t < 160) {
        float v[10];
        #pragma unroll
        for (int m = 0; m < 10; m++) {
            float a = gBias[m];
            #pragma unroll
            for (int g = 0; g < 8; g++)
                a += W4[(g * 160 + t) * 11 + m];
            v[m] = a;
        }
        float mx = v[0];
        #pragma unroll
        for (int m = 1; m < 10; m++) mx = fmaxf(mx, v[m]);
        float s = 0.f;
        #pragma unroll
        for (int m = 0; m < 10; m++) { float e = __expf(v[m] - mx); v[m] = e; s += e; }
        float inv = 1.f / s;
        float* wr = WS + t * 12;
        size_t wo = (size_t)row * 1600 + (size_t)t * 10;
        #pragma unroll
        for (int m = 0; m < 10; m++) {
            float wv = v[m] * inv;
            wr[m] = wv;
            out[W_OFF1 + wo + m] = wv;
            out[W_OFF2 + wo + m] = wv;
        }
    }
    __syncthreads();

    // ---- shiftmap gather + BN + tanh: thread = (k, group of 20 j) ----
    {
        const int k  = t & 63;
        const int g  = t >> 6;             // 0..7
        const int j0 = g * 20;

        float sc = gGamma[k] / sqrtf(gVar[k] + 1e-3f);
        float sh = gBeta[k] - gMean[k] * sc;

        const float* Lc = Qt + k * QROW + 2;       // data columns
        const float* Rc = Qt + (64 + k) * QROW + 2;

        float lw[5], rw[5];
        #pragma unroll
        for (int s = 0; s < 5; s++) {
            int li = j0 - s; if (li < 0) li += 160;
            lw[s] = Lc[li];
            rw[s] = Rc[j0 + s];            // j0+s <= 144, no wrap at init
        }

        float* xout = out + (size_t)(row * 160 + j0) * 64 + k;
        #pragma unroll
        for (int jj = 0; jj < 20; jj++) {
            int j = j0 + jj;
            const unsigned long long* wp =
                reinterpret_cast<const unsigned long long*>(WS + j * 12);
            unsigned long long a = 0ull;
            #pragma unroll
            for (int s = 0; s < 5; s++)
                fma2(a, wp[s], pack2(lw[s], rw[s]));
            float lo, hi;
            unpack2(a, lo, hi);
            float x = (lo + hi) * sc + sh;
            float e = __expf(2.f * x);     // tanh = 1 - 2/(e^{2x}+1)
            xout[(size_t)jj * 64] = 1.f - 2.f / (e + 1.f);

            int ln = j + 1; if (ln >= 160) ln -= 160;
            int rn = j + 5; if (rn >= 160) rn -= 160;
            lw[4] = lw[3]; lw[3] = lw[2]; lw[2] = lw[1]; lw[1] = lw[0];
            lw[0] = Lc[ln];
            rw[0] = rw[1]; rw[1] = rw[2]; rw[2] = rw[3]; rw[3] = rw[4];
            rw[4] = Rc[rn];
        }
    }
}

extern "C" void kernel_launch(void* const* d_in, const int* in_sizes, int n_in,
                              void* d_out, int out_size)
{
    const float* L     = (const float*)d_in[0];
    const float* R     = (const float*)d_in[1];
    const float* K     = (const float*)d_in[2];
    const float* bias  = (const float*)d_in[3];
    const float* gamma = (const float*)d_in[4];
    const float* beta  = (const float*)d_in[5];
    const float* mean  = (const float*)d_in[6];
    const float* var   = (const float*)d_in[7];
    float* out = (float*)d_out;

    const int smem = (128 * QROW + 128 * KROW + 8 * 160 * 11 + 160 * 12) * 4; // 175104 B
    cudaFuncSetAttribute(ea_kernel, cudaFuncAttributeMaxDynamicSharedMemorySize, smem);
    ea_kernel<<<512, NTHR, smem>>>(L, R, K, bias, gamma, beta, mean, var, out);
}